// round 9
// baseline (speedup 1.0000x reference)
#include <cuda_runtime.h>
#include <math.h>
#include <stdint.h>

#define B 64
#define T 512
#define F 512
#define H 1024
#define G4 4096   // 4*H
#define NBLK 64   // persistent blocks (all co-resident; 64 <= 148 SMs)
#define NTHR 512

// ---------------- scratch (device globals; no allocations) ----------------
__device__ float g_pre[(size_t)T * G4 * B];          // [t][j][b], 512 MB
__device__ float g_Wh0r[(size_t)G4 * H];             // tf32-rounded weights
__device__ float g_Wi1r[(size_t)G4 * H];
__device__ float g_Wh1r[(size_t)G4 * H];
// Recurrent state, TRANSPOSED layout [h][b]; ping-pong by t parity.
// h buffers hold tf32-ROUNDED values. c is full fp32.
__device__ float g_h0A[H * B];
__device__ float g_h0B[H * B];
__device__ float g_h1A[H * B];
__device__ float g_h1B[H * B];
__device__ float g_c0[H * B];
__device__ float g_c1[H * B];
__device__ float g_h0F[H * B];   // full-precision h at t=T-1
__device__ float g_h1F[H * B];
__device__ unsigned g_barCnt;
__device__ unsigned g_barGen;

// ---------------- small helpers ----------------
__device__ __forceinline__ float to_tf32(float x) {
    uint32_t u;
    asm("cvt.rna.tf32.f32 %0, %1;" : "=r"(u) : "f"(x));
    return __uint_as_float(u);
}
__device__ __forceinline__ float sigmoidf_(float v) {
    return 1.f / (1.f + expf(-v));
}
__device__ __forceinline__ void cp16(void* sdst, const void* gsrc) {
    uint32_t s = (uint32_t)__cvta_generic_to_shared(sdst);
    asm volatile("cp.async.cg.shared.global [%0], [%1], 16;\n" :: "r"(s), "l"(gsrc));
}
__device__ __forceinline__ void cp_commit() {
    asm volatile("cp.async.commit_group;\n");
}
template <int N> __device__ __forceinline__ void cp_wait() {
    asm volatile("cp.async.wait_group %0;\n" :: "n"(N));
}
__device__ __forceinline__ void mma_tf32(float c[4],
                                         uint32_t a0, uint32_t a1, uint32_t a2, uint32_t a3,
                                         uint32_t b0, uint32_t b1) {
    asm volatile(
        "mma.sync.aligned.m16n8k8.row.col.f32.tf32.tf32.f32 "
        "{%0,%1,%2,%3}, {%4,%5,%6,%7}, {%8,%9}, {%0,%1,%2,%3};\n"
        : "+f"(c[0]), "+f"(c[1]), "+f"(c[2]), "+f"(c[3])
        : "r"(a0), "r"(a1), "r"(a2), "r"(a3), "r"(b0), "r"(b1));
}

// ---------------- init kernels ----------------
__global__ void init_state() {
    int i = blockIdx.x * blockDim.x + threadIdx.x;
    if (i < H * B) {
        g_h0A[i] = 0.f; g_h0B[i] = 0.f;
        g_h1A[i] = 0.f; g_h1B[i] = 0.f;
        g_c0[i]  = 0.f; g_c1[i]  = 0.f;
    }
    if (i == 0) { g_barCnt = 0u; g_barGen = 0u; }
}

__global__ void round_weights(const float* __restrict__ Wh0,
                              const float* __restrict__ Wi1,
                              const float* __restrict__ Wh1) {
    size_t i = (size_t)blockIdx.x * blockDim.x + threadIdx.x;
    if (i < (size_t)G4 * H) {
        g_Wh0r[i] = to_tf32(Wh0[i]);
        g_Wi1r[i] = to_tf32(Wi1[i]);
        g_Wh1r[i] = to_tf32(Wh1[i]);
    }
}

// ---------------- precompute: g_pre[t][j][b] = x @ Wi0^T + (bi0+bh0) ------
__global__ void precompute_kernel(const float* __restrict__ x,
                                  const float* __restrict__ Wi,
                                  const float* __restrict__ bi,
                                  const float* __restrict__ bh) {
    __shared__ float xs[16][132];
    __shared__ float ws[16][68];
    __shared__ float sgp[128][65];

    const int tid = threadIdx.x;
    const int tx  = tid & 15;
    const int ty  = tid >> 4;
    const int n0  = tx * 4;
    const int m0  = ty * 8;
    const int rBase = blockIdx.y * 128;
    const int nBase = blockIdx.x * 64;

    float acc[8][4];
#pragma unroll
    for (int i = 0; i < 8; i++)
#pragma unroll
        for (int j = 0; j < 4; j++) acc[i][j] = 0.f;

    for (int kb = 0; kb < F; kb += 16) {
#pragma unroll
        for (int it = 0; it < 2; it++) {
            int i = tid + it * 256;
            int m = i >> 2, kq = i & 3;
            int b = m & 63, tIdx = (rBase >> 6) + (m >> 6);
            float4 v = *(const float4*)&x[((size_t)b * T + tIdx) * F + kb + kq * 4];
            xs[kq * 4 + 0][m] = v.x; xs[kq * 4 + 1][m] = v.y;
            xs[kq * 4 + 2][m] = v.z; xs[kq * 4 + 3][m] = v.w;
        }
        {
            int n = tid >> 2, kq = tid & 3;
            float4 v = *(const float4*)&Wi[(size_t)(nBase + n) * F + kb + kq * 4];
            ws[kq * 4 + 0][n] = v.x; ws[kq * 4 + 1][n] = v.y;
            ws[kq * 4 + 2][n] = v.z; ws[kq * 4 + 3][n] = v.w;
        }
        __syncthreads();
#pragma unroll
        for (int k = 0; k < 16; k++) {
            float4 a0 = *(const float4*)&xs[k][m0];
            float4 a1 = *(const float4*)&xs[k][m0 + 4];
            float4 b4 = *(const float4*)&ws[k][n0];
            float am[8] = {a0.x, a0.y, a0.z, a0.w, a1.x, a1.y, a1.z, a1.w};
            float bn[4] = {b4.x, b4.y, b4.z, b4.w};
#pragma unroll
            for (int i = 0; i < 8; i++)
#pragma unroll
                for (int j = 0; j < 4; j++)
                    acc[i][j] = fmaf(am[i], bn[j], acc[i][j]);
        }
        __syncthreads();
    }

    float bias[4];
#pragma unroll
    for (int j = 0; j < 4; j++) bias[j] = bi[nBase + n0 + j] + bh[nBase + n0 + j];

#pragma unroll
    for (int i = 0; i < 8; i++)
#pragma unroll
        for (int j = 0; j < 4; j++)
            sgp[m0 + i][n0 + j] = acc[i][j] + bias[j];
    __syncthreads();

#pragma unroll
    for (int rep = 0; rep < 32; rep++) {
        int flat = rep * 256 + tid;
        int b = flat & 63;
        int col = flat >> 6;
        int colIdx = col & 63;
        int tHalf = col >> 6;
        int m = tHalf * 64 + b;
        int tIdx = (rBase >> 6) + tHalf;
        g_pre[((size_t)tIdx * G4 + nBase + colIdx) * 64 + b] = sgp[m][colIdx];
    }
}

// ---------------- grid barrier ----------------
__device__ __forceinline__ void grid_sync() {
    __threadfence();
    __syncthreads();
    if (threadIdx.x == 0) {
        unsigned gen = *(volatile unsigned*)&g_barGen;
        unsigned a = atomicAdd(&g_barCnt, 1u);
        if (a == NBLK - 1) {
            g_barCnt = 0u;
            __threadfence();
            atomicAdd(&g_barGen, 1u);
        } else {
            while (*(volatile unsigned*)&g_barGen == gen) { }
        }
    }
    __syncthreads();
}

// ---------------- tf32 MMA GEMM, 4-stage pipelined, 1 sync/chunk ----------
// Block tile C[64 m][64 n], K = 1024 per segment (NSEG segments fused).
// A layout: [k][64 m] (transposed h). W rounded, [4H][H], block rows
// j = (r>>4)*H + hBase + (r&15), r in [0,64).
#define HS_STR 72
#define WS_STR 68
#define HS_BUF (64 * HS_STR)
#define WS_BUF (64 * WS_STR)

__device__ __forceinline__ void gemm_prefetch(const float* __restrict__ A,
                                              const float* __restrict__ Wr,
                                              float* hp, float* wp,
                                              int c, int hBase, int tid) {
#pragma unroll
    for (int it = 0; it < 2; it++) {
        int i = tid + it * NTHR;
        int k = i >> 4, mq = i & 15;
        cp16(&hp[k * HS_STR + mq * 4], A + (size_t)(c * 64 + k) * 64 + mq * 4);
    }
#pragma unroll
    for (int it = 0; it < 2; it++) {
        int i = tid + it * NTHR;
        int r = i >> 4, kq = i & 15;
        const float* src = Wr + (size_t)((r >> 4) * H + hBase + (r & 15)) * H + c * 64 + kq * 4;
        cp16(&wp[r * WS_STR + kq * 4], src);
    }
    cp_commit();
}

__device__ __forceinline__ void pf_seg(const float* A0, const float* W0,
                                       const float* A1, const float* W1,
                                       float* hs4, float* ws4,
                                       int cc, int hBase, int tid) {
    const float* A = (cc < 16) ? A0 : A1;
    const float* W = (cc < 16) ? W0 : W1;
    gemm_prefetch(A, W, hs4 + (size_t)(cc & 3) * HS_BUF,
                  ws4 + (size_t)(cc & 3) * WS_BUF, cc & 15, hBase, tid);
}

__device__ __forceinline__ void gemm_compute(const float* hp, const float* wp,
                                             float acc[2][4], int lane, int warp) {
    const int g  = lane >> 2;
    const int tg = lane & 3;
    const int mB = (warp & 3) * 16;
    const int nB = (warp >> 2) * 16;
#pragma unroll
    for (int k8 = 0; k8 < 8; k8++) {
        int k0 = k8 * 8;
        uint32_t a0 = __float_as_uint(hp[(k0 + tg) * HS_STR + mB + g]);
        uint32_t a1 = __float_as_uint(hp[(k0 + tg) * HS_STR + mB + g + 8]);
        uint32_t a2 = __float_as_uint(hp[(k0 + tg + 4) * HS_STR + mB + g]);
        uint32_t a3 = __float_as_uint(hp[(k0 + tg + 4) * HS_STR + mB + g + 8]);
#pragma unroll
        for (int ni = 0; ni < 2; ni++) {
            uint32_t b0 = __float_as_uint(wp[(nB + ni * 8 + g) * WS_STR + k0 + tg]);
            uint32_t b1 = __float_as_uint(wp[(nB + ni * 8 + g) * WS_STR + k0 + tg + 4]);
            mma_tf32(acc[ni], a0, a1, a2, a3, b0, b1);
        }
    }
}

// NSEG segments of 16 chunks each, one continuous 4-stage pipeline.
// Distance-2 prefetch; ONE __syncthreads per chunk (4 buffers make the
// write-after-read hazard safe: writer hits buf (cc+2)&3, slowest reader
// is on buf (cc-1)&3; difference 3 mod 4 != 0).
template <int NSEG>
__device__ __forceinline__ void gemm_run(const float* A0, const float* W0,
                                         const float* A1, const float* W1,
                                         float* hs4, float* ws4,
                                         float acc[2][4],
                                         int hBase, int tid, int lane, int warp) {
    const int NC = NSEG * 16;
    pf_seg(A0, W0, A1, W1, hs4, ws4, 0, hBase, tid);
    pf_seg(A0, W0, A1, W1, hs4, ws4, 1, hBase, tid);
#pragma unroll 1
    for (int cc = 0; cc < NC; cc++) {
        if (cc + 2 < NC) {
            pf_seg(A0, W0, A1, W1, hs4, ws4, cc + 2, hBase, tid);
            cp_wait<2>();
        } else if (cc + 2 == NC) {
            cp_wait<1>();
        } else {
            cp_wait<0>();
        }
        __syncthreads();
        gemm_compute(hs4 + (size_t)(cc & 3) * HS_BUF,
                     ws4 + (size_t)(cc & 3) * WS_BUF, acc, lane, warp);
    }
}

// ---------------- persistent LSTM kernel ----------------
// 64 blocks x 512 threads; block owns 16 h-cols (hBase) x 4 gates = 64 W rows.
// 16 warps in 4m x 4n grid, warp tile 16x16.
__global__ void __launch_bounds__(NTHR, 1)
lstm_persistent(const float* __restrict__ bi1,
                const float* __restrict__ bh1,
                float* __restrict__ out) {
    extern __shared__ float smem[];
    float* hs4 = smem;                        // 4 * HS_BUF
    float* ws4 = hs4 + 4 * HS_BUF;            // 4 * WS_BUF
    float* sg  = ws4 + 4 * WS_BUF;            // 64 * 65

    const int tid  = threadIdx.x;
    const int lane = tid & 31;
    const int warp = tid >> 5;
    const int hBase = blockIdx.x * 16;
    const int g  = lane >> 2;
    const int tg = lane & 3;
    const int mB = (warp & 3) * 16;
    const int nB = (warp >> 2) * 16;

    // layer-1 biases for this thread's epilogue cells: n_e = (tid>>6) + e*8
    float bs1[2][4];
#pragma unroll
    for (int e = 0; e < 2; e++) {
        int n = (tid >> 6) + e * 8;
#pragma unroll
        for (int q = 0; q < 4; q++) {
            int j = q * H + hBase + n;
            bs1[e][q] = bi1[j] + bh1[j];
        }
    }

    for (int it = 0; it <= T; it++) {
        // ---- layer 0, t = it ----
        if (it < T) {
            const int t = it;
            const float* hin  = (t & 1) ? g_h0B : g_h0A;
            float*       hout = (t & 1) ? g_h0A : g_h0B;

            float acc[2][4];
#pragma unroll
            for (int i = 0; i < 2; i++)
#pragma unroll
                for (int j = 0; j < 4; j++) acc[i][j] = 0.f;

            gemm_run<1>(hin, g_Wh0r, hin, g_Wh0r, hs4, ws4, acc, hBase, tid, lane, warp);

#pragma unroll
            for (int ni = 0; ni < 2; ni++) {
                int col = nB + ni * 8 + 2 * tg;
                sg[(mB + g) * 65 + col]         = acc[ni][0];
                sg[(mB + g) * 65 + col + 1]     = acc[ni][1];
                sg[(mB + g + 8) * 65 + col]     = acc[ni][2];
                sg[(mB + g + 8) * 65 + col + 1] = acc[ni][3];
            }
            __syncthreads();

            const float* pre = &g_pre[(size_t)t * G4 * 64];
#pragma unroll
            for (int e = 0; e < 2; e++) {
                int idx = tid + e * NTHR;
                int n = idx >> 6, m = idx & 63;
                size_t pb = (size_t)(hBase + n) * 64 + m;
                float iv = sg[m * 65 + n]      + pre[pb];
                float fv = sg[m * 65 + 16 + n] + pre[pb + (size_t)H * 64];
                float gv = sg[m * 65 + 32 + n] + pre[pb + 2 * (size_t)H * 64];
                float ov = sg[m * 65 + 48 + n] + pre[pb + 3 * (size_t)H * 64];
                int gidx = (hBase + n) * 64 + m;
                float cP = g_c0[gidx];
                float cN = sigmoidf_(fv) * cP + sigmoidf_(iv) * tanhf(gv);
                float hN = sigmoidf_(ov) * tanhf(cN);
                g_c0[gidx] = cN;
                hout[gidx] = to_tf32(hN);
                if (t == T - 1) g_h0F[gidx] = hN;
            }
            __syncthreads();
        }

        // ---- layer 1, t = it-1 (fused Wi1 + Wh1 pipeline) ----
        if (it > 0) {
            const int t = it - 1;
            const float* h0new = (t & 1) ? g_h0A : g_h0B;
            const float* h1in  = (t & 1) ? g_h1B : g_h1A;
            float*       h1out = (t & 1) ? g_h1A : g_h1B;

            float acc[2][4];
#pragma unroll
            for (int i = 0; i < 2; i++)
#pragma unroll
                for (int j = 0; j < 4; j++) acc[i][j] = 0.f;

            gemm_run<2>(h0new, g_Wi1r, h1in, g_Wh1r, hs4, ws4, acc, hBase, tid, lane, warp);

#pragma unroll
            for (int ni = 0; ni < 2; ni++) {
                int col = nB + ni * 8 + 2 * tg;
                sg[(mB + g) * 65 + col]         = acc[ni][0];
                sg[(mB + g) * 65 + col + 1]     = acc[ni][1];
                sg[(mB + g + 8) * 65 + col]     = acc[ni][2];
                sg[(mB + g + 8) * 65 + col + 1] = acc[ni][3];
            }
            __syncthreads();

#pragma unroll
            for (int e = 0; e < 2; e++) {
                int idx = tid + e * NTHR;
                int n = idx >> 6, m = idx & 63;
                float iv = sg[m * 65 + n]      + bs1[e][0];
                float fv = sg[m * 65 + 16 + n] + bs1[e][1];
                float gv = sg[m * 65 + 32 + n] + bs1[e][2];
                float ov = sg[m * 65 + 48 + n] + bs1[e][3];
                int gidx = (hBase + n) * 64 + m;
                float cP = g_c1[gidx];
                float cN = sigmoidf_(fv) * cP + sigmoidf_(iv) * tanhf(gv);
                float hN = sigmoidf_(ov) * tanhf(cN);
                g_c1[gidx] = cN;
                h1out[gidx] = to_tf32(hN);
                if (t == T - 1) g_h1F[gidx] = hN;
                out[((size_t)m * T + t) * H + hBase + n] = hN;   // out[b][t][h]
            }
            __syncthreads();
        }

        if (it < T) grid_sync();
    }

    // ---- finals: hT [2,B,H] then cT [2,B,H]. Own columns only. ----
    {
        size_t off = (size_t)B * T * H;
        size_t BH = (size_t)B * H;
#pragma unroll
        for (int e = 0; e < 2; e++) {
            int idx = tid + e * NTHR;
            int n = idx >> 6, m = idx & 63;
            int hIdx = hBase + n;
            int gidx = hIdx * 64 + m;
            size_t p = (size_t)m * H + hIdx;
            out[off + p]          = g_h0F[gidx];
            out[off + BH + p]     = g_h1F[gidx];
            out[off + 2 * BH + p] = g_c0[gidx];
            out[off + 3 * BH + p] = g_c1[gidx];
        }
    }
}

// ---------------- launch ----------------
extern "C" void kernel_launch(void* const* d_in, const int* in_sizes, int n_in,
                              void* d_out, int out_size) {
    const float* x   = (const float*)d_in[0];
    const float* Wi0 = (const float*)d_in[1];
    const float* Wh0 = (const float*)d_in[2];
    const float* bi0 = (const float*)d_in[3];
    const float* bh0 = (const float*)d_in[4];
    const float* Wi1 = (const float*)d_in[5];
    const float* Wh1 = (const float*)d_in[6];
    const float* bi1 = (const float*)d_in[7];
    const float* bh1 = (const float*)d_in[8];
    float* out = (float*)d_out;

    const int smemBytes = (4 * (HS_BUF + WS_BUF) + 64 * 65) * 4;  // 160,000 B
    cudaFuncSetAttribute(lstm_persistent,
                         cudaFuncAttributeMaxDynamicSharedMemorySize, smemBytes);

    init_state<<<(H * B + 255) / 256, 256>>>();
    round_weights<<<(G4 * H + 255) / 256, 256>>>(Wh0, Wi1, Wh1);
    precompute_kernel<<<dim3(G4 / 64, (B * T) / 128), 256>>>(x, Wi0, bi0, bh0);
    lstm_persistent<<<NBLK, NTHR, smemBytes>>>(bi1, bh1, out);
}

// round 12
// speedup vs baseline: 1.8054x; 1.8054x over previous
#include <cuda_runtime.h>
#include <cuda_fp16.h>
#include <math.h>
#include <stdint.h>

#define B 64
#define T 512
#define F 512
#define H 1024
#define G4 4096   // 4*H
#define NBLK 64   // persistent blocks (all co-resident; 64 <= 148 SMs)
#define NTHR 256

// ---------------- scratch (device globals; no allocations) ----------------
__device__ float g_pre[(size_t)T * G4 * B];           // [t][j][b] fp32, 512 MB
// fp16 packed operands
__device__ __half g_xh[(size_t)B * T * F];            // [m=t*64+b][f]
__device__ __half g_Wi0h[(size_t)G4 * F];             // [j][f]
__device__ __half g_Wh0P[(size_t)NBLK * 64 * H];      // [blk][r][k], r=gate-packed
__device__ __half g_Wi1P[(size_t)NBLK * 64 * H];
__device__ __half g_Wh1P[(size_t)NBLK * 64 * H];
// Recurrent h state as fp16, layout [b][k] (k contiguous); ping-pong by parity.
__device__ __half g_h0A[B * H];
__device__ __half g_h0B[B * H];
__device__ __half g_h1A[B * H];
__device__ __half g_h1B[B * H];
// c state fp32, block-private layout [k][b]
__device__ float g_c0[H * B];
__device__ float g_c1[H * B];
// Full-precision final h (captured at t = T-1)
__device__ float g_h0F[H * B];
__device__ float g_h1F[H * B];
__device__ unsigned g_barCnt;
__device__ unsigned g_barGen;

// ---------------- helpers ----------------
__device__ __forceinline__ float sigmoidf_(float v) {
    return 1.f / (1.f + expf(-v));
}
__device__ __forceinline__ void cp16(void* sdst, const void* gsrc) {
    uint32_t s = (uint32_t)__cvta_generic_to_shared(sdst);
    asm volatile("cp.async.cg.shared.global [%0], [%1], 16;\n" :: "r"(s), "l"(gsrc));
}
__device__ __forceinline__ void cp_commit() {
    asm volatile("cp.async.commit_group;\n");
}
template <int N> __device__ __forceinline__ void cp_wait() {
    asm volatile("cp.async.wait_group %0;\n" :: "n"(N));
}
// mma m16n8k16 f16 inputs, f32 accum
__device__ __forceinline__ void mma_f16(float c[4],
                                        uint32_t a0, uint32_t a1, uint32_t a2, uint32_t a3,
                                        uint32_t b0, uint32_t b1) {
    asm volatile(
        "mma.sync.aligned.m16n8k16.row.col.f32.f16.f16.f32 "
        "{%0,%1,%2,%3}, {%4,%5,%6,%7}, {%8,%9}, {%0,%1,%2,%3};\n"
        : "+f"(c[0]), "+f"(c[1]), "+f"(c[2]), "+f"(c[3])
        : "r"(a0), "r"(a1), "r"(a2), "r"(a3), "r"(b0), "r"(b1));
}

// ---------------- init / conversion kernels ----------------
__global__ void init_state() {
    int i = blockIdx.x * blockDim.x + threadIdx.x;
    if (i < H * B) {
        g_h0A[i] = __float2half(0.f); g_h0B[i] = __float2half(0.f);
        g_h1A[i] = __float2half(0.f); g_h1B[i] = __float2half(0.f);
        g_c0[i]  = 0.f; g_c1[i]  = 0.f;
    }
    if (i == 0) { g_barCnt = 0u; g_barGen = 0u; }
}

// x[b][t][f] -> g_xh[m=t*64+b][f] fp16
__global__ void cvt_x(const float* __restrict__ x) {
    size_t i = (size_t)blockIdx.x * blockDim.x + threadIdx.x;
    if (i >= (size_t)B * T * F) return;
    int f = (int)(i & (F - 1));
    int t = (int)((i >> 9) & (T - 1));
    int b = (int)(i >> 18);
    g_xh[((size_t)(t * 64 + b)) * F + f] = __float2half_rn(x[i]);
}

__global__ void cvt_wi0(const float* __restrict__ Wi0) {
    size_t i = (size_t)blockIdx.x * blockDim.x + threadIdx.x;
    if (i < (size_t)G4 * F) g_Wi0h[i] = __float2half_rn(Wi0[i]);
}

// pack recurrent weights into per-block row order: r -> j = (r>>4)*H + blk*16 + (r&15)
__global__ void pack_w(const float* __restrict__ Wh0,
                       const float* __restrict__ Wi1,
                       const float* __restrict__ Wh1) {
    size_t i = (size_t)blockIdx.x * blockDim.x + threadIdx.x;
    if (i >= (size_t)NBLK * 64 * H) return;
    int k = (int)(i & (H - 1));
    int r = (int)((i >> 10) & 63);
    int blk = (int)(i >> 16);
    size_t j = (size_t)((r >> 4) * H + blk * 16 + (r & 15));
    g_Wh0P[i] = __float2half_rn(Wh0[j * H + k]);
    g_Wi1P[i] = __float2half_rn(Wi1[j * H + k]);
    g_Wh1P[i] = __float2half_rn(Wh1[j * H + k]);
}

// ---------------- fp16 tensor precompute: g_pre[t][j][b] = x@Wi0^T + bias ----
// Block tile 128m x 64n, K=512 (8 chunks of 64). 256 thr, 8 warps of 32x32.
#define XS_STR 72   // halves
__global__ void __launch_bounds__(NTHR)
precompute_kernel(const float* __restrict__ bi, const float* __restrict__ bh) {
    extern __shared__ __half smemh[];
    __half* xs = smemh;                         // 2 bufs x 128*72
    __half* ws = smemh + 2 * 128 * XS_STR;      // 2 bufs x 64*72
    __shared__ float biasS[64];

    const int tid = threadIdx.x;
    const int lane = tid & 31;
    const int warp = tid >> 5;
    const int g  = lane >> 2;
    const int tg = lane & 3;
    const int mB = (warp & 3) * 32;
    const int nB = (warp >> 2) * 32;
    const int rBase = blockIdx.y * 128;
    const int nBase = blockIdx.x * 64;

    if (tid < 64) biasS[tid] = bi[nBase + tid] + bh[nBase + tid];

    float acc[2][4][4];
#pragma unroll
    for (int mi = 0; mi < 2; mi++)
#pragma unroll
        for (int ni = 0; ni < 4; ni++)
#pragma unroll
            for (int j = 0; j < 4; j++) acc[mi][ni][j] = 0.f;

    auto prefetch = [&](int c) {
        __half* xp = xs + (c & 1) * 128 * XS_STR;
        __half* wp = ws + (c & 1) * 64 * XS_STR;
#pragma unroll
        for (int it = 0; it < 4; it++) {
            int i = tid + it * NTHR;           // 0..1023
            int r = i >> 3, q = i & 7;
            cp16(&xp[r * XS_STR + q * 8], g_xh + (size_t)(rBase + r) * F + c * 64 + q * 8);
        }
#pragma unroll
        for (int it = 0; it < 2; it++) {
            int i = tid + it * NTHR;           // 0..511
            int r = i >> 3, q = i & 7;
            cp16(&wp[r * XS_STR + q * 8], g_Wi0h + (size_t)(nBase + r) * F + c * 64 + q * 8);
        }
        cp_commit();
    };

    prefetch(0);
#pragma unroll 1
    for (int c = 0; c < 8; c++) {
        if (c < 7) { prefetch(c + 1); cp_wait<1>(); }
        else       { cp_wait<0>(); }
        __syncthreads();
        const __half* xp = xs + (c & 1) * 128 * XS_STR;
        const __half* wp = ws + (c & 1) * 64 * XS_STR;
#pragma unroll
        for (int kk = 0; kk < 4; kk++) {
            int k0 = kk * 16;
            uint32_t a[2][4], b[4][2];
#pragma unroll
            for (int mi = 0; mi < 2; mi++) {
                const __half* base = xp + (mB + mi * 16 + g) * XS_STR + k0 + 2 * tg;
                a[mi][0] = *(const uint32_t*)(base);
                a[mi][1] = *(const uint32_t*)(base + 8 * XS_STR);
                a[mi][2] = *(const uint32_t*)(base + 8);
                a[mi][3] = *(const uint32_t*)(base + 8 * XS_STR + 8);
            }
#pragma unroll
            for (int ni = 0; ni < 4; ni++) {
                const __half* base = wp + (nB + ni * 8 + g) * XS_STR + k0 + 2 * tg;
                b[ni][0] = *(const uint32_t*)(base);
                b[ni][1] = *(const uint32_t*)(base + 8);
            }
#pragma unroll
            for (int mi = 0; mi < 2; mi++)
#pragma unroll
                for (int ni = 0; ni < 4; ni++)
                    mma_f16(acc[mi][ni], a[mi][0], a[mi][1], a[mi][2], a[mi][3],
                            b[ni][0], b[ni][1]);
        }
        __syncthreads();
    }

    // stage to sgp[128][65] fp32 (aliases operand buffers — all reads done)
    float* sgp = (float*)smemh;
#pragma unroll
    for (int mi = 0; mi < 2; mi++)
#pragma unroll
        for (int ni = 0; ni < 4; ni++) {
            int row = mB + mi * 16 + g;
            int col = nB + ni * 8 + 2 * tg;
            sgp[row * 65 + col]           = acc[mi][ni][0];
            sgp[row * 65 + col + 1]       = acc[mi][ni][1];
            sgp[(row + 8) * 65 + col]     = acc[mi][ni][2];
            sgp[(row + 8) * 65 + col + 1] = acc[mi][ni][3];
        }
    __syncthreads();

#pragma unroll
    for (int rep = 0; rep < 32; rep++) {
        int flat = rep * NTHR + tid;           // [0, 8192)
        int b = flat & 63;
        int col = flat >> 6;                   // [0, 128)
        int colIdx = col & 63;
        int tHalf = col >> 6;
        int m = tHalf * 64 + b;
        int tIdx = (rBase >> 6) + tHalf;
        g_pre[((size_t)tIdx * G4 + nBase + colIdx) * 64 + b] =
            sgp[m * 65 + colIdx] + biasS[colIdx];
    }
}

// ---------------- grid barrier ----------------
__device__ __forceinline__ void grid_sync() {
    __threadfence();
    __syncthreads();
    if (threadIdx.x == 0) {
        unsigned gen = *(volatile unsigned*)&g_barGen;
        unsigned a = atomicAdd(&g_barCnt, 1u);
        if (a == NBLK - 1) {
            g_barCnt = 0u;
            __threadfence();
            atomicAdd(&g_barGen, 1u);
        } else {
            while (*(volatile unsigned*)&g_barGen == gen) { }
        }
    }
    __syncthreads();
}

// ---------------- fp16 MMA GEMM, 4-stage pipeline, 1 sync/chunk -----------
// Block tile C[64 m(batch)][64 n(gate-rows)], K segments of 1024.
// hs/ws smem layout [row][k] halves, stride 72 (conflict-free fragments).
#define HS_STRH 72
#define HS_BUFH (64 * HS_STRH)

__device__ __forceinline__ void gemm_prefetch(const __half* __restrict__ A,
                                              const __half* __restrict__ Wp,
                                              __half* hp, __half* wp,
                                              int c, int tid) {
#pragma unroll
    for (int it = 0; it < 2; it++) {
        int i = tid + it * NTHR;               // 0..511
        int r = i >> 3, q = i & 7;
        cp16(&hp[r * HS_STRH + q * 8], A + (size_t)r * H + c * 64 + q * 8);
    }
#pragma unroll
    for (int it = 0; it < 2; it++) {
        int i = tid + it * NTHR;
        int r = i >> 3, q = i & 7;
        cp16(&wp[r * HS_STRH + q * 8], Wp + (size_t)r * H + c * 64 + q * 8);
    }
    cp_commit();
}

__device__ __forceinline__ void pf_seg(const __half* A0, const __half* W0,
                                       const __half* A1, const __half* W1,
                                       __half* hs4, __half* ws4,
                                       int cc, int tid) {
    const __half* A = (cc < 16) ? A0 : A1;
    const __half* W = (cc < 16) ? W0 : W1;
    gemm_prefetch(A, W, hs4 + (size_t)(cc & 3) * HS_BUFH,
                  ws4 + (size_t)(cc & 3) * HS_BUFH, cc & 15, tid);
}

// 8 warps, warp tile 32m x 16n: mB = (warp&1)*32, nB = (warp>>1)*16
__device__ __forceinline__ void gemm_compute(const __half* hp, const __half* wp,
                                             float acc[2][2][4], int lane, int warp) {
    const int g  = lane >> 2;
    const int tg = lane & 3;
    const int mB = (warp & 1) * 32;
    const int nB = (warp >> 1) * 16;
#pragma unroll
    for (int kk = 0; kk < 4; kk++) {
        int k0 = kk * 16;
        uint32_t a[2][4], b[2][2];
#pragma unroll
        for (int mi = 0; mi < 2; mi++) {
            const __half* base = hp + (mB + mi * 16 + g) * HS_STRH + k0 + 2 * tg;
            a[mi][0] = *(const uint32_t*)(base);
            a[mi][1] = *(const uint32_t*)(base + 8 * HS_STRH);
            a[mi][2] = *(const uint32_t*)(base + 8);
            a[mi][3] = *(const uint32_t*)(base + 8 * HS_STRH + 8);
        }
#pragma unroll
        for (int ni = 0; ni < 2; ni++) {
            const __half* base = wp + (nB + ni * 8 + g) * HS_STRH + k0 + 2 * tg;
            b[ni][0] = *(const uint32_t*)(base);
            b[ni][1] = *(const uint32_t*)(base + 8);
        }
#pragma unroll
        for (int mi = 0; mi < 2; mi++)
#pragma unroll
            for (int ni = 0; ni < 2; ni++)
                mma_f16(acc[mi][ni], a[mi][0], a[mi][1], a[mi][2], a[mi][3],
                        b[ni][0], b[ni][1]);
    }
}

template <int NSEG>
__device__ __forceinline__ void gemm_run(const __half* A0, const __half* W0,
                                         const __half* A1, const __half* W1,
                                         __half* hs4, __half* ws4,
                                         float acc[2][2][4],
                                         int tid, int lane, int warp) {
    const int NC = NSEG * 16;
    pf_seg(A0, W0, A1, W1, hs4, ws4, 0, tid);
    pf_seg(A0, W0, A1, W1, hs4, ws4, 1, tid);
#pragma unroll 1
    for (int cc = 0; cc < NC; cc++) {
        if (cc + 2 < NC) {
            pf_seg(A0, W0, A1, W1, hs4, ws4, cc + 2, tid);
            cp_wait<2>();
        } else if (cc + 2 == NC) {
            cp_wait<1>();
        } else {
            cp_wait<0>();
        }
        __syncthreads();
        gemm_compute(hs4 + (size_t)(cc & 3) * HS_BUFH,
                     ws4 + (size_t)(cc & 3) * HS_BUFH, acc, lane, warp);
    }
}

// ---------------- persistent LSTM kernel ----------------
__global__ void __launch_bounds__(NTHR, 1)
lstm_persistent(const float* __restrict__ bi1,
                const float* __restrict__ bh1,
                float* __restrict__ out) {
    extern __shared__ __half smemh[];
    __half* hs4 = smemh;                       // 4 * HS_BUFH halves
    __half* ws4 = smemh + 4 * HS_BUFH;         // 4 * HS_BUFH halves
    float*  sg  = (float*)(smemh + 8 * HS_BUFH);  // 64*65 fp32

    const int tid  = threadIdx.x;
    const int lane = tid & 31;
    const int warp = tid >> 5;
    const int hBase = blockIdx.x * 16;
    const int g  = lane >> 2;
    const int tg = lane & 3;
    const int mB = (warp & 1) * 32;
    const int nB = (warp >> 1) * 16;

    const __half* Wh0P = g_Wh0P + (size_t)blockIdx.x * 64 * H;
    const __half* Wi1P = g_Wi1P + (size_t)blockIdx.x * 64 * H;
    const __half* Wh1P = g_Wh1P + (size_t)blockIdx.x * 64 * H;

    // layer-1 biases for epilogue cells: n = (idx>>6), idx = tid + e*256
    float bs1[4][4];
#pragma unroll
    for (int e = 0; e < 4; e++) {
        int n = (tid + e * NTHR) >> 6;
#pragma unroll
        for (int q = 0; q < 4; q++) {
            int j = q * H + hBase + n;
            bs1[e][q] = bi1[j] + bh1[j];
        }
    }

    for (int it = 0; it <= T; it++) {
        // ---- layer 0, t = it ----
        if (it < T) {
            const int t = it;
            const __half* hin  = (t & 1) ? g_h0B : g_h0A;
            __half*       hout = (t & 1) ? g_h0A : g_h0B;

            float acc[2][2][4];
#pragma unroll
            for (int a_ = 0; a_ < 2; a_++)
#pragma unroll
                for (int b_ = 0; b_ < 2; b_++)
#pragma unroll
                    for (int j = 0; j < 4; j++) acc[a_][b_][j] = 0.f;

            gemm_run<1>(hin, Wh0P, hin, Wh0P, hs4, ws4, acc, tid, lane, warp);

#pragma unroll
            for (int mi = 0; mi < 2; mi++)
#pragma unroll
                for (int ni = 0; ni < 2; ni++) {
                    int row = mB + mi * 16 + g;
                    int col = nB + ni * 8 + 2 * tg;
                    sg[row * 65 + col]           = acc[mi][ni][0];
                    sg[row * 65 + col + 1]       = acc[mi][ni][1];
                    sg[(row + 8) * 65 + col]     = acc[mi][ni][2];
                    sg[(row + 8) * 65 + col + 1] = acc[mi][ni][3];
                }
            __syncthreads();

            const float* pre = &g_pre[(size_t)t * G4 * 64];
#pragma unroll
            for (int e = 0; e < 4; e++) {
                int idx = tid + e * NTHR;
                int n = idx >> 6, m = idx & 63;
                size_t pb = (size_t)(hBase + n) * 64 + m;
                float iv = sg[m * 65 + n]      + pre[pb];
                float fv = sg[m * 65 + 16 + n] + pre[pb + (size_t)H * 64];
                float gv = sg[m * 65 + 32 + n] + pre[pb + 2 * (size_t)H * 64];
                float ov = sg[m * 65 + 48 + n] + pre[pb + 3 * (size_t)H * 64];
                int gidx = (hBase + n) * 64 + m;
                float cP = g_c0[gidx];
                float cN = sigmoidf_(fv) * cP + sigmoidf_(iv) * tanhf(gv);
                float hN = sigmoidf_(ov) * tanhf(cN);
                g_c0[gidx] = cN;
                hout[(size_t)m * H + hBase + n] = __float2half_rn(hN);
                if (t == T - 1) g_h0F[gidx] = hN;
            }
            __syncthreads();
        }

        // ---- layer 1, t = it-1 (fused Wi1 + Wh1 pipeline, 32 chunks) ----
        if (it > 0) {
            const int t = it - 1;
            const __half* h0new = (t & 1) ? g_h0A : g_h0B;
            const __half* h1in  = (t & 1) ? g_h1B : g_h1A;
            __half*       h1out = (t & 1) ? g_h1A : g_h1B;

            float acc[2][2][4];
#pragma unroll
            for (int a_ = 0; a_ < 2; a_++)
#pragma unroll
                for (int b_ = 0; b_ < 2; b_++)
#pragma unroll
                    for (int j = 0; j < 4; j++) acc[a_][b_][j] = 0.f;

            gemm_run<2>(h0new, Wi1P, h1in, Wh1P, hs4, ws4, acc, tid, lane, warp);

#pragma unroll
            for (int mi = 0; mi < 2; mi++)
#pragma unroll
                for (int ni = 0; ni < 2; ni++) {
                    int row = mB + mi * 16 + g;
                    int col = nB + ni * 8 + 2 * tg;
                    sg[row * 65 + col]           = acc[mi][ni][0];
                    sg[row * 65 + col + 1]       = acc[mi][ni][1];
                    sg[(row + 8) * 65 + col]     = acc[mi][ni][2];
                    sg[(row + 8) * 65 + col + 1] = acc[mi][ni][3];
                }
            __syncthreads();

#pragma unroll
            for (int e = 0; e < 4; e++) {
                int idx = tid + e * NTHR;
                int n = idx >> 6, m = idx & 63;
                float iv = sg[m * 65 + n]      + bs1[e][0];
                float fv = sg[m * 65 + 16 + n] + bs1[e][1];
                float gv = sg[m * 65 + 32 + n] + bs1[e][2];
                float ov = sg[m * 65 + 48 + n] + bs1[e][3];
                int gidx = (hBase + n) * 64 + m;
                float cP = g_c1[gidx];
                float cN = sigmoidf_(fv) * cP + sigmoidf_(iv) * tanhf(gv);
                float hN = sigmoidf_(ov) * tanhf(cN);
                g_c1[gidx] = cN;
                h1out[(size_t)m * H + hBase + n] = __float2half_rn(hN);
                if (t == T - 1) g_h1F[gidx] = hN;
                out[((size_t)m * T + t) * H + hBase + n] = hN;   // out[b][t][h]
            }
            __syncthreads();
        }

        if (it < T) grid_sync();
    }

    // ---- finals: hT [2,B,H] then cT [2,B,H]. Own columns only. ----
    {
        size_t off = (size_t)B * T * H;
        size_t BH = (size_t)B * H;
#pragma unroll
        for (int e = 0; e < 4; e++) {
            int idx = tid + e * NTHR;
            int n = idx >> 6, m = idx & 63;
            int hIdx = hBase + n;
            int gidx = hIdx * 64 + m;
            size_t p = (size_t)m * H + hIdx;
            out[off + p]          = g_h0F[gidx];
            out[off + BH + p]     = g_h1F[gidx];
            out[off + 2 * BH + p] = g_c0[gidx];
            out[off + 3 * BH + p] = g_c1[gidx];
        }
    }
}

// ---------------- launch ----------------
extern "C" void kernel_launch(void* const* d_in, const int* in_sizes, int n_in,
                              void* d_out, int out_size) {
    const float* x   = (const float*)d_in[0];
    const float* Wi0 = (const float*)d_in[1];
    const float* Wh0 = (const float*)d_in[2];
    const float* bi0 = (const float*)d_in[3];
    const float* bh0 = (const float*)d_in[4];
    const float* Wi1 = (const float*)d_in[5];
    const float* Wh1 = (const float*)d_in[6];
    const float* bi1 = (const float*)d_in[7];
    const float* bh1 = (const float*)d_in[8];
    float* out = (float*)d_out;

    // persistent kernel smem: 8 bufs of 64*72 halves + 64*65 fp32
    const int smemLoop = 8 * HS_BUFH * 2 + 64 * 65 * 4;       // 73728 + 16640
    cudaFuncSetAttribute(lstm_persistent,
                         cudaFuncAttributeMaxDynamicSharedMemorySize, smemLoop);
    // precompute smem: 2*(128+64)*72 halves
    const int smemPre = 2 * (128 + 64) * XS_STR * 2;          // 55296
    cudaFuncSetAttribute(precompute_kernel,
                         cudaFuncAttributeMaxDynamicSharedMemorySize, smemPre);

    init_state<<<(H * B + 255) / 256, 256>>>();
    cvt_x<<<(B * T * F + 255) / 256, 256>>>(x);
    cvt_wi0<<<(G4 * F + 255) / 256, 256>>>(Wi0);
    pack_w<<<(NBLK * 64 * H + 255) / 256, 256>>>(Wh0, Wi1, Wh1);
    precompute_kernel<<<dim3(G4 / 64, (B * T) / 128), NTHR, smemPre>>>(bi0, bh0);
    lstm_persistent<<<NBLK, NTHR, smemLoop>>>(bi1, bh1, out);
}